// round 1
// baseline (speedup 1.0000x reference)
#include <cuda_runtime.h>
#include <cstddef>

#define Bv 4
#define Sv 1024
#define Dv 768
#define Hv 12
#define DHv 64
#define Mv 4096   // B*S
#define BHv 48    // B*H

// ---------------- scratch (device globals; no allocation allowed) ------------
__device__ float g_q[Mv * Dv];              // also reused as pre-LN buffer
__device__ float g_k[Mv * Dv];
__device__ float g_v[Mv * Dv];
__device__ float g_ctx[Mv * Dv];
__device__ float g_att[(size_t)BHv * Sv * Sv];  // scores then final probs (192 MB)

// ---------------- block reduction helper (256 threads) -----------------------
__device__ __forceinline__ float blockReduce256(float v, bool domax, float* sh) {
    const int lane = threadIdx.x & 31;
    const int w = threadIdx.x >> 5;
#pragma unroll
    for (int o = 16; o > 0; o >>= 1) {
        float u = __shfl_xor_sync(0xffffffffu, v, o);
        v = domax ? fmaxf(v, u) : (v + u);
    }
    if (lane == 0) sh[w] = v;
    __syncthreads();
    if (w == 0) {
        float x = (lane < 8) ? sh[lane] : (domax ? -3.4e38f : 0.f);
#pragma unroll
        for (int o = 4; o > 0; o >>= 1) {
            float u = __shfl_xor_sync(0xffffffffu, x, o);
            x = domax ? fmaxf(x, u) : (x + u);
        }
        if (lane == 0) sh[8] = x;
    }
    __syncthreads();
    return sh[8];
}

// ---------------- generic 64x64x16 SGEMM: out = A@W + bias (+resid) ----------
// A: [M,K] row-major, W: [K,N] row-major.
// headLayout: out[((b*H+h)*S+s)*DH+d]  (row m -> b,s ; col -> h,d)
__global__ __launch_bounds__(256) void gemm_proj(
    const float* __restrict__ A, const float* __restrict__ W,
    const float* __restrict__ bias, const float* __restrict__ resid,
    float* __restrict__ out, int M, int N, int K, int headLayout)
{
    __shared__ float As[16][65];  // [k][m] transposed
    __shared__ float Bs[16][65];  // [k][n]
    const int tid = threadIdx.x;
    const int tx = tid & 15, ty = tid >> 4;
    const int n0 = blockIdx.x * 64, m0 = blockIdx.y * 64;
    const int lam = tid >> 2;          // row within tile (0..63)
    const int lak = (tid & 3) * 4;     // k offset (0,4,8,12)

    float acc[4][4];
#pragma unroll
    for (int i = 0; i < 4; ++i)
#pragma unroll
        for (int j = 0; j < 4; ++j) acc[i][j] = 0.f;

    for (int k0 = 0; k0 < K; k0 += 16) {
        float4 av = *reinterpret_cast<const float4*>(A + (size_t)(m0 + lam) * K + k0 + lak);
        As[lak + 0][lam] = av.x;
        As[lak + 1][lam] = av.y;
        As[lak + 2][lam] = av.z;
        As[lak + 3][lam] = av.w;
#pragma unroll
        for (int it = 0; it < 4; ++it) {
            int idx = tid + it * 256;
            int r = idx >> 6, c = idx & 63;
            Bs[r][c] = W[(size_t)(k0 + r) * N + n0 + c];
        }
        __syncthreads();
#pragma unroll
        for (int k = 0; k < 16; ++k) {
            float a0 = As[k][ty * 4 + 0], a1 = As[k][ty * 4 + 1];
            float a2 = As[k][ty * 4 + 2], a3 = As[k][ty * 4 + 3];
            float b0 = Bs[k][tx * 4 + 0], b1 = Bs[k][tx * 4 + 1];
            float b2 = Bs[k][tx * 4 + 2], b3 = Bs[k][tx * 4 + 3];
            acc[0][0] += a0 * b0; acc[0][1] += a0 * b1; acc[0][2] += a0 * b2; acc[0][3] += a0 * b3;
            acc[1][0] += a1 * b0; acc[1][1] += a1 * b1; acc[1][2] += a1 * b2; acc[1][3] += a1 * b3;
            acc[2][0] += a2 * b0; acc[2][1] += a2 * b1; acc[2][2] += a2 * b2; acc[2][3] += a2 * b3;
            acc[3][0] += a3 * b0; acc[3][1] += a3 * b1; acc[3][2] += a3 * b2; acc[3][3] += a3 * b3;
        }
        __syncthreads();
    }

    const int col = n0 + tx * 4;
    float4 bv = *reinterpret_cast<const float4*>(bias + col);
#pragma unroll
    for (int i = 0; i < 4; ++i) {
        int row = m0 + ty * 4 + i;
        float4 v = make_float4(acc[i][0] + bv.x, acc[i][1] + bv.y,
                               acc[i][2] + bv.z, acc[i][3] + bv.w);
        if (resid) {
            float4 rv = *reinterpret_cast<const float4*>(resid + (size_t)row * N + col);
            v.x += rv.x; v.y += rv.y; v.z += rv.z; v.w += rv.w;
        }
        if (headLayout) {
            int b = row >> 10, s = row & 1023;
            int h = col >> 6, d = col & 63;
            *reinterpret_cast<float4*>(out + ((size_t)(b * Hv + h) * Sv + s) * DHv + d) = v;
        } else {
            *reinterpret_cast<float4*>(out + (size_t)row * N + col) = v;
        }
    }
}

// ---------------- scores = Q @ K^T / 8, per (b,h) ----------------------------
__global__ __launch_bounds__(256) void qk_scores(
    const float* __restrict__ Q, const float* __restrict__ Km, float* __restrict__ att)
{
    __shared__ float Qs[64][65];  // [dh][m]
    __shared__ float Ks[64][65];  // [dh][n]
    const int tid = threadIdx.x;
    const int tx = tid & 15, ty = tid >> 4;
    const int k0 = blockIdx.x * 64, q0 = blockIdx.y * 64;
    const size_t base = (size_t)blockIdx.z * Sv * DHv;

#pragma unroll
    for (int it = 0; it < 16; ++it) {
        int idx = tid + it * 256;
        int m = idx >> 6, c = idx & 63;
        Qs[c][m] = Q[base + (size_t)(q0 + m) * DHv + c];
        Ks[c][m] = Km[base + (size_t)(k0 + m) * DHv + c];
    }
    __syncthreads();

    float acc[4][4];
#pragma unroll
    for (int i = 0; i < 4; ++i)
#pragma unroll
        for (int j = 0; j < 4; ++j) acc[i][j] = 0.f;

#pragma unroll 16
    for (int d = 0; d < 64; ++d) {
        float a0 = Qs[d][ty * 4 + 0], a1 = Qs[d][ty * 4 + 1];
        float a2 = Qs[d][ty * 4 + 2], a3 = Qs[d][ty * 4 + 3];
        float b0 = Ks[d][tx * 4 + 0], b1 = Ks[d][tx * 4 + 1];
        float b2 = Ks[d][tx * 4 + 2], b3 = Ks[d][tx * 4 + 3];
        acc[0][0] += a0 * b0; acc[0][1] += a0 * b1; acc[0][2] += a0 * b2; acc[0][3] += a0 * b3;
        acc[1][0] += a1 * b0; acc[1][1] += a1 * b1; acc[1][2] += a1 * b2; acc[1][3] += a1 * b3;
        acc[2][0] += a2 * b0; acc[2][1] += a2 * b1; acc[2][2] += a2 * b2; acc[2][3] += a2 * b3;
        acc[3][0] += a3 * b0; acc[3][1] += a3 * b1; acc[3][2] += a3 * b2; acc[3][3] += a3 * b3;
    }

    const size_t ob = ((size_t)blockIdx.z * Sv + q0 + ty * 4) * Sv + k0 + tx * 4;
#pragma unroll
    for (int i = 0; i < 4; ++i) {
        float4 v = make_float4(acc[i][0] * 0.125f, acc[i][1] * 0.125f,
                               acc[i][2] * 0.125f, acc[i][3] * 0.125f);
        *reinterpret_cast<float4*>(att + ob + (size_t)i * Sv) = v;
    }
}

// ---- softmax(scores+mask) -> mix with conv(prev) -> softmax again (in place)
__global__ __launch_bounds__(256) void mix_softmax(
    float* __restrict__ att, const float* __restrict__ prev,
    const float* __restrict__ mask, const float* __restrict__ cw_g,
    const float* __restrict__ cb_g)
{
    __shared__ float cw[144];
    __shared__ float cb[12];
    __shared__ float red[9];
    const int t = threadIdx.x;
    const int q = blockIdx.x;
    const int b = blockIdx.y;
    if (t < 144) cw[t] = cw_g[t];
    if (t < 12) cb[t] = cb_g[t];
    __syncthreads();

    // load previous_attention for all 12 heads at this (b, q) row
    float pv[12][4];
#pragma unroll
    for (int i = 0; i < 12; ++i) {
        const float* pp = prev + ((size_t)(b * Hv + i) * Sv + q) * Sv;
#pragma unroll
        for (int j = 0; j < 4; ++j) pv[i][j] = pp[t + 256 * j];
    }
    // 1x1 conv over head channels, in place: pv[o] = conv_w[o,:] . pv[:,j] + cb[o]
#pragma unroll
    for (int j = 0; j < 4; ++j) {
        float tmp[12];
#pragma unroll
        for (int o = 0; o < 12; ++o) {
            float a = cb[o];
#pragma unroll
            for (int i = 0; i < 12; ++i) a += cw[o * 12 + i] * pv[i][j];
            tmp[o] = a;
        }
#pragma unroll
        for (int o = 0; o < 12; ++o) pv[o][j] = tmp[o];
    }

    float mk[4];
#pragma unroll
    for (int j = 0; j < 4; ++j) mk[j] = mask[(size_t)b * Sv + t + 256 * j];

#pragma unroll
    for (int o = 0; o < 12; ++o) {
        const size_t rb = ((size_t)(b * Hv + o) * Sv + q) * Sv + t;
        float s[4];
#pragma unroll
        for (int j = 0; j < 4; ++j) s[j] = att[rb + 256 * j] + mk[j];

        float mx = fmaxf(fmaxf(s[0], s[1]), fmaxf(s[2], s[3]));
        mx = blockReduce256(mx, true, red);
        float e[4], ls = 0.f;
#pragma unroll
        for (int j = 0; j < 4; ++j) { e[j] = __expf(s[j] - mx); ls += e[j]; }
        float sum1 = blockReduce256(ls, false, red);
        float inv1 = 1.f / sum1;

        float mixd[4];
#pragma unroll
        for (int j = 0; j < 4; ++j) mixd[j] = 0.5f * pv[o][j] + 0.5f * (e[j] * inv1);

        float mx2 = fmaxf(fmaxf(mixd[0], mixd[1]), fmaxf(mixd[2], mixd[3]));
        mx2 = blockReduce256(mx2, true, red);
        float e2[4], ls2 = 0.f;
#pragma unroll
        for (int j = 0; j < 4; ++j) { e2[j] = __expf(mixd[j] - mx2); ls2 += e2[j]; }
        float sum2 = blockReduce256(ls2, false, red);
        float inv2 = 1.f / sum2;
#pragma unroll
        for (int j = 0; j < 4; ++j) att[rb + 256 * j] = e2[j] * inv2;
    }
}

// ---------------- ctx = probs @ V, per (b,h); out in [B,S,D] -----------------
__global__ __launch_bounds__(256) void av_ctx(
    const float* __restrict__ P, const float* __restrict__ V, float* __restrict__ ctx)
{
    __shared__ float Ps[16][65];  // [k][m]
    __shared__ float Vs[16][65];  // [k][d]
    const int tid = threadIdx.x;
    const int tx = tid & 15, ty = tid >> 4;
    const int q0 = blockIdx.x * 64;
    const int bh = blockIdx.y;
    const int b = bh / Hv, h = bh % Hv;
    const size_t pbase = (size_t)bh * Sv * Sv;
    const size_t vbase = (size_t)bh * Sv * DHv;
    const int lam = tid >> 2;
    const int lak = (tid & 3) * 4;

    float acc[4][4];
#pragma unroll
    for (int i = 0; i < 4; ++i)
#pragma unroll
        for (int j = 0; j < 4; ++j) acc[i][j] = 0.f;

    for (int k0 = 0; k0 < Sv; k0 += 16) {
        float4 av = *reinterpret_cast<const float4*>(P + pbase + (size_t)(q0 + lam) * Sv + k0 + lak);
        Ps[lak + 0][lam] = av.x;
        Ps[lak + 1][lam] = av.y;
        Ps[lak + 2][lam] = av.z;
        Ps[lak + 3][lam] = av.w;
#pragma unroll
        for (int it = 0; it < 4; ++it) {
            int idx = tid + it * 256;
            int r = idx >> 6, c = idx & 63;
            Vs[r][c] = V[vbase + (size_t)(k0 + r) * DHv + c];
        }
        __syncthreads();
#pragma unroll
        for (int k = 0; k < 16; ++k) {
            float a0 = Ps[k][ty * 4 + 0], a1 = Ps[k][ty * 4 + 1];
            float a2 = Ps[k][ty * 4 + 2], a3 = Ps[k][ty * 4 + 3];
            float b0 = Vs[k][tx * 4 + 0], b1 = Vs[k][tx * 4 + 1];
            float b2 = Vs[k][tx * 4 + 2], b3 = Vs[k][tx * 4 + 3];
            acc[0][0] += a0 * b0; acc[0][1] += a0 * b1; acc[0][2] += a0 * b2; acc[0][3] += a0 * b3;
            acc[1][0] += a1 * b0; acc[1][1] += a1 * b1; acc[1][2] += a1 * b2; acc[1][3] += a1 * b3;
            acc[2][0] += a2 * b0; acc[2][1] += a2 * b1; acc[2][2] += a2 * b2; acc[2][3] += a2 * b3;
            acc[3][0] += a3 * b0; acc[3][1] += a3 * b1; acc[3][2] += a3 * b2; acc[3][3] += a3 * b3;
        }
        __syncthreads();
    }

#pragma unroll
    for (int i = 0; i < 4; ++i) {
        int qrow = q0 + ty * 4 + i;
        float4 v = make_float4(acc[i][0], acc[i][1], acc[i][2], acc[i][3]);
        *reinterpret_cast<float4*>(ctx + ((size_t)b * Sv + qrow) * Dv + h * DHv + tx * 4) = v;
    }
}

// ---------------- LayerNorm over last dim (768) -------------------------------
__global__ __launch_bounds__(256) void layernorm_row(
    const float* __restrict__ pre, const float* __restrict__ w,
    const float* __restrict__ bb, float* __restrict__ out)
{
    __shared__ float red[9];
    const int t = threadIdx.x;
    const size_t row = blockIdx.x;
    const float* x = pre + row * Dv;

    float v[3];
#pragma unroll
    for (int j = 0; j < 3; ++j) v[j] = x[t + 256 * j];
    float s = v[0] + v[1] + v[2];
    s = blockReduce256(s, false, red);
    float u = s * (1.f / 768.f);
    float d0 = v[0] - u, d1 = v[1] - u, d2 = v[2] - u;
    float sq = d0 * d0 + d1 * d1 + d2 * d2;
    sq = blockReduce256(sq, false, red);
    float var = sq * (1.f / 768.f);
    float r = rsqrtf(var + 1e-12f);
    float dd[3] = {d0, d1, d2};
#pragma unroll
    for (int j = 0; j < 3; ++j) {
        int c = t + 256 * j;
        out[row * Dv + c] = dd[j] * r * w[c] + bb[c];
    }
}

// ------------------------------------------------------------------------------
extern "C" void kernel_launch(void* const* d_in, const int* in_sizes, int n_in,
                              void* d_out, int out_size)
{
    const float* hidden = (const float*)d_in[0];
    const float* mask   = (const float*)d_in[1];
    const float* prev   = (const float*)d_in[2];
    const float* Wq = (const float*)d_in[3];
    const float* bq = (const float*)d_in[4];
    const float* Wk = (const float*)d_in[5];
    const float* bk = (const float*)d_in[6];
    const float* Wv = (const float*)d_in[7];
    const float* bv = (const float*)d_in[8];
    const float* cw = (const float*)d_in[9];
    const float* cb = (const float*)d_in[10];
    const float* Wo = (const float*)d_in[11];
    const float* bo = (const float*)d_in[12];
    const float* lnw = (const float*)d_in[13];
    const float* lnb = (const float*)d_in[14];
    float* out = (float*)d_out;

    float *q, *k, *v, *att, *ctx;
    cudaGetSymbolAddress((void**)&q,   g_q);
    cudaGetSymbolAddress((void**)&k,   g_k);
    cudaGetSymbolAddress((void**)&v,   g_v);
    cudaGetSymbolAddress((void**)&att, g_att);
    cudaGetSymbolAddress((void**)&ctx, g_ctx);

    dim3 gProj(Dv / 64, Mv / 64);  // (12, 64)
    gemm_proj<<<gProj, 256>>>(hidden, Wq, bq, nullptr, q, Mv, Dv, Dv, 1);
    gemm_proj<<<gProj, 256>>>(hidden, Wk, bk, nullptr, k, Mv, Dv, Dv, 1);
    gemm_proj<<<gProj, 256>>>(hidden, Wv, bv, nullptr, v, Mv, Dv, Dv, 1);

    qk_scores<<<dim3(Sv / 64, Sv / 64, BHv), 256>>>(q, k, att);

    mix_softmax<<<dim3(Sv, Bv), 256>>>(att, prev, mask, cw, cb);

    av_ctx<<<dim3(Sv / 64, BHv), 256>>>(att, v, ctx);

    // out-projection + bias + residual into g_q (q no longer needed)
    gemm_proj<<<gProj, 256>>>(ctx, Wo, bo, hidden, q, Mv, Dv, Dv, 0);

    layernorm_row<<<Mv, 256>>>(q, lnw, lnb, out);
}

// round 2
// speedup vs baseline: 1.4482x; 1.4482x over previous
#include <cuda_runtime.h>
#include <cstddef>

#define Bv 4
#define Sv 1024
#define Dv 768
#define Hv 12
#define DHv 64
#define Mv 4096   // B*S
#define BHv 48    // B*H

// ---------------- scratch (device globals; no allocation allowed) ------------
__device__ float g_q[Mv * Dv];              // also reused as pre-LN buffer
__device__ float g_k[Mv * Dv];
__device__ float g_v[Mv * Dv];
__device__ float g_ctx[Mv * Dv];
__device__ float g_att[(size_t)BHv * Sv * Sv];  // scores then final probs (192 MB)

// ---------------- block reduction helper (256 threads) -----------------------
__device__ __forceinline__ float blockReduce256(float v, bool domax, float* sh) {
    const int lane = threadIdx.x & 31;
    const int w = threadIdx.x >> 5;
#pragma unroll
    for (int o = 16; o > 0; o >>= 1) {
        float u = __shfl_xor_sync(0xffffffffu, v, o);
        v = domax ? fmaxf(v, u) : (v + u);
    }
    if (lane == 0) sh[w] = v;
    __syncthreads();
    if (w == 0) {
        float x = (lane < 8) ? sh[lane] : (domax ? -3.4e38f : 0.f);
#pragma unroll
        for (int o = 4; o > 0; o >>= 1) {
            float u = __shfl_xor_sync(0xffffffffu, x, o);
            x = domax ? fmaxf(x, u) : (x + u);
        }
        if (lane == 0) sh[8] = x;
    }
    __syncthreads();
    return sh[8];
}

// ================= 128x128x16 SGEMM body, 256 thr, 8x8 micro =================
// A: [M,K] row-major. W: [K,N] row-major. out: bias(+resid), row-major or
// head layout [B,H,S,DH].
__device__ __forceinline__ void gemm128_body(
    const float* __restrict__ A, const float* __restrict__ W,
    const float* __restrict__ bias, const float* __restrict__ resid,
    float* __restrict__ out, int K, int N, int headLayout,
    int m0, int n0)
{
    __shared__ float As[16][132];
    __shared__ float Bs[16][128];
    const int tid = threadIdx.x;
    const int tx = tid & 15, ty = tid >> 4;
    const int r  = tid >> 2;            // 0..63
    const int kq = (tid & 3) * 4;       // 0,4,8,12
    const int brow = tid >> 5;          // 0..7
    const int bcol = (tid & 31) * 4;    // 0..124

    float acc[8][8];
#pragma unroll
    for (int i = 0; i < 8; ++i)
#pragma unroll
        for (int j = 0; j < 8; ++j) acc[i][j] = 0.f;

    for (int k0 = 0; k0 < K; k0 += 16) {
        float4 a0 = *reinterpret_cast<const float4*>(A + (size_t)(m0 + r) * K + k0 + kq);
        float4 a1 = *reinterpret_cast<const float4*>(A + (size_t)(m0 + r + 64) * K + k0 + kq);
        As[kq + 0][r] = a0.x; As[kq + 1][r] = a0.y; As[kq + 2][r] = a0.z; As[kq + 3][r] = a0.w;
        As[kq + 0][r + 64] = a1.x; As[kq + 1][r + 64] = a1.y;
        As[kq + 2][r + 64] = a1.z; As[kq + 3][r + 64] = a1.w;

        float4 b0 = *reinterpret_cast<const float4*>(W + (size_t)(k0 + brow) * N + n0 + bcol);
        float4 b1 = *reinterpret_cast<const float4*>(W + (size_t)(k0 + brow + 8) * N + n0 + bcol);
        *reinterpret_cast<float4*>(&Bs[brow][bcol]) = b0;
        *reinterpret_cast<float4*>(&Bs[brow + 8][bcol]) = b1;
        __syncthreads();

#pragma unroll
        for (int k = 0; k < 16; ++k) {
            float4 fa0 = *reinterpret_cast<const float4*>(&As[k][ty * 4]);
            float4 fa1 = *reinterpret_cast<const float4*>(&As[k][ty * 4 + 64]);
            float4 fb0 = *reinterpret_cast<const float4*>(&Bs[k][tx * 4]);
            float4 fb1 = *reinterpret_cast<const float4*>(&Bs[k][tx * 4 + 64]);
            float a[8] = {fa0.x, fa0.y, fa0.z, fa0.w, fa1.x, fa1.y, fa1.z, fa1.w};
            float b[8] = {fb0.x, fb0.y, fb0.z, fb0.w, fb1.x, fb1.y, fb1.z, fb1.w};
#pragma unroll
            for (int i = 0; i < 8; ++i)
#pragma unroll
                for (int j = 0; j < 8; ++j) acc[i][j] += a[i] * b[j];
        }
        __syncthreads();
    }

#pragma unroll
    for (int qj = 0; qj < 2; ++qj) {
        const int col = n0 + qj * 64 + tx * 4;
        float4 bv = *reinterpret_cast<const float4*>(bias + col);
#pragma unroll
        for (int qi = 0; qi < 2; ++qi) {
#pragma unroll
            for (int i = 0; i < 4; ++i) {
                int row = m0 + qi * 64 + ty * 4 + i;
                int ai = qi * 4 + i;
                float4 v = make_float4(acc[ai][qj * 4 + 0] + bv.x,
                                       acc[ai][qj * 4 + 1] + bv.y,
                                       acc[ai][qj * 4 + 2] + bv.z,
                                       acc[ai][qj * 4 + 3] + bv.w);
                if (resid) {
                    float4 rv = *reinterpret_cast<const float4*>(resid + (size_t)row * N + col);
                    v.x += rv.x; v.y += rv.y; v.z += rv.z; v.w += rv.w;
                }
                if (headLayout) {
                    int b = row >> 10, s = row & 1023;
                    int h = col >> 6, d = col & 63;
                    *reinterpret_cast<float4*>(out + ((size_t)(b * Hv + h) * Sv + s) * DHv + d) = v;
                } else {
                    *reinterpret_cast<float4*>(out + (size_t)row * N + col) = v;
                }
            }
        }
    }
}

// fused Q/K/V projection: blockIdx.z selects which weight/out
__global__ __launch_bounds__(256) void gemm_qkv(
    const float* __restrict__ A,
    const float* __restrict__ Wq, const float* __restrict__ bq,
    const float* __restrict__ Wk, const float* __restrict__ bk,
    const float* __restrict__ Wv, const float* __restrict__ bv,
    float* __restrict__ q, float* __restrict__ k, float* __restrict__ v)
{
    const float* W; const float* bb; float* o;
    if (blockIdx.z == 0)      { W = Wq; bb = bq; o = q; }
    else if (blockIdx.z == 1) { W = Wk; bb = bk; o = k; }
    else                      { W = Wv; bb = bv; o = v; }
    gemm128_body(A, W, bb, nullptr, o, Dv, Dv, 1, blockIdx.y * 128, blockIdx.x * 128);
}

// output projection + residual
__global__ __launch_bounds__(256) void gemm_out(
    const float* __restrict__ A, const float* __restrict__ W,
    const float* __restrict__ bias, const float* __restrict__ resid,
    float* __restrict__ out)
{
    gemm128_body(A, W, bias, resid, out, Dv, Dv, 0, blockIdx.y * 128, blockIdx.x * 128);
}

// ============ scores = Q @ K^T / 8, per (b,h), 128x128 tiles =================
__global__ __launch_bounds__(256) void qk128(
    const float* __restrict__ Q, const float* __restrict__ Km, float* __restrict__ att)
{
    __shared__ float As[16][132];
    __shared__ float Bs[16][132];
    const int tid = threadIdx.x;
    const int tx = tid & 15, ty = tid >> 4;
    const int r  = tid >> 2;
    const int kq = (tid & 3) * 4;
    const int n0 = blockIdx.x * 128, m0 = blockIdx.y * 128;
    const size_t base = (size_t)blockIdx.z * Sv * DHv;

    float acc[8][8];
#pragma unroll
    for (int i = 0; i < 8; ++i)
#pragma unroll
        for (int j = 0; j < 8; ++j) acc[i][j] = 0.f;

#pragma unroll
    for (int k0 = 0; k0 < DHv; k0 += 16) {
        float4 a0 = *reinterpret_cast<const float4*>(Q + base + (size_t)(m0 + r) * DHv + k0 + kq);
        float4 a1 = *reinterpret_cast<const float4*>(Q + base + (size_t)(m0 + r + 64) * DHv + k0 + kq);
        As[kq + 0][r] = a0.x; As[kq + 1][r] = a0.y; As[kq + 2][r] = a0.z; As[kq + 3][r] = a0.w;
        As[kq + 0][r + 64] = a1.x; As[kq + 1][r + 64] = a1.y;
        As[kq + 2][r + 64] = a1.z; As[kq + 3][r + 64] = a1.w;

        float4 b0 = *reinterpret_cast<const float4*>(Km + base + (size_t)(n0 + r) * DHv + k0 + kq);
        float4 b1 = *reinterpret_cast<const float4*>(Km + base + (size_t)(n0 + r + 64) * DHv + k0 + kq);
        Bs[kq + 0][r] = b0.x; Bs[kq + 1][r] = b0.y; Bs[kq + 2][r] = b0.z; Bs[kq + 3][r] = b0.w;
        Bs[kq + 0][r + 64] = b1.x; Bs[kq + 1][r + 64] = b1.y;
        Bs[kq + 2][r + 64] = b1.z; Bs[kq + 3][r + 64] = b1.w;
        __syncthreads();

#pragma unroll
        for (int k = 0; k < 16; ++k) {
            float4 fa0 = *reinterpret_cast<const float4*>(&As[k][ty * 4]);
            float4 fa1 = *reinterpret_cast<const float4*>(&As[k][ty * 4 + 64]);
            float4 fb0 = *reinterpret_cast<const float4*>(&Bs[k][tx * 4]);
            float4 fb1 = *reinterpret_cast<const float4*>(&Bs[k][tx * 4 + 64]);
            float a[8] = {fa0.x, fa0.y, fa0.z, fa0.w, fa1.x, fa1.y, fa1.z, fa1.w};
            float b[8] = {fb0.x, fb0.y, fb0.z, fb0.w, fb1.x, fb1.y, fb1.z, fb1.w};
#pragma unroll
            for (int i = 0; i < 8; ++i)
#pragma unroll
                for (int j = 0; j < 8; ++j) acc[i][j] += a[i] * b[j];
        }
        __syncthreads();
    }

    const size_t ab = (size_t)blockIdx.z * Sv * Sv;
#pragma unroll
    for (int qi = 0; qi < 2; ++qi) {
#pragma unroll
        for (int i = 0; i < 4; ++i) {
            int row = m0 + qi * 64 + ty * 4 + i;
            int ai = qi * 4 + i;
#pragma unroll
            for (int qj = 0; qj < 2; ++qj) {
                int col = n0 + qj * 64 + tx * 4;
                float4 v = make_float4(acc[ai][qj * 4 + 0] * 0.125f,
                                       acc[ai][qj * 4 + 1] * 0.125f,
                                       acc[ai][qj * 4 + 2] * 0.125f,
                                       acc[ai][qj * 4 + 3] * 0.125f);
                *reinterpret_cast<float4*>(att + ab + (size_t)row * Sv + col) = v;
            }
        }
    }
}

// ---- softmax(scores+mask) -> mix with conv(prev) -> softmax again (in place)
__global__ __launch_bounds__(256) void mix_softmax(
    float* __restrict__ att, const float* __restrict__ prev,
    const float* __restrict__ mask, const float* __restrict__ cw_g,
    const float* __restrict__ cb_g)
{
    __shared__ float cw[144];
    __shared__ float cb[12];
    __shared__ float red[9];
    const int t = threadIdx.x;
    const int q = blockIdx.x;
    const int b = blockIdx.y;
    if (t < 144) cw[t] = cw_g[t];
    if (t < 12) cb[t] = cb_g[t];
    __syncthreads();

    float pv[12][4];
#pragma unroll
    for (int i = 0; i < 12; ++i) {
        const float* pp = prev + ((size_t)(b * Hv + i) * Sv + q) * Sv;
#pragma unroll
        for (int j = 0; j < 4; ++j) pv[i][j] = pp[t + 256 * j];
    }
#pragma unroll
    for (int j = 0; j < 4; ++j) {
        float tmp[12];
#pragma unroll
        for (int o = 0; o < 12; ++o) {
            float a = cb[o];
#pragma unroll
            for (int i = 0; i < 12; ++i) a += cw[o * 12 + i] * pv[i][j];
            tmp[o] = a;
        }
#pragma unroll
        for (int o = 0; o < 12; ++o) pv[o][j] = tmp[o];
    }

    float mk[4];
#pragma unroll
    for (int j = 0; j < 4; ++j) mk[j] = mask[(size_t)b * Sv + t + 256 * j];

#pragma unroll
    for (int o = 0; o < 12; ++o) {
        const size_t rb = ((size_t)(b * Hv + o) * Sv + q) * Sv + t;
        float s[4];
#pragma unroll
        for (int j = 0; j < 4; ++j) s[j] = att[rb + 256 * j] + mk[j];

        float mx = fmaxf(fmaxf(s[0], s[1]), fmaxf(s[2], s[3]));
        mx = blockReduce256(mx, true, red);
        float e[4], ls = 0.f;
#pragma unroll
        for (int j = 0; j < 4; ++j) { e[j] = __expf(s[j] - mx); ls += e[j]; }
        float sum1 = blockReduce256(ls, false, red);
        float inv1 = 1.f / sum1;

        float mixd[4];
#pragma unroll
        for (int j = 0; j < 4; ++j) mixd[j] = 0.5f * pv[o][j] + 0.5f * (e[j] * inv1);

        float mx2 = fmaxf(fmaxf(mixd[0], mixd[1]), fmaxf(mixd[2], mixd[3]));
        mx2 = blockReduce256(mx2, true, red);
        float e2[4], ls2 = 0.f;
#pragma unroll
        for (int j = 0; j < 4; ++j) { e2[j] = __expf(mixd[j] - mx2); ls2 += e2[j]; }
        float sum2 = blockReduce256(ls2, false, red);
        float inv2 = 1.f / sum2;
#pragma unroll
        for (int j = 0; j < 4; ++j) att[rb + 256 * j] = e2[j] * inv2;
    }
}

// ============ ctx = probs @ V, per (b,h), 128x64 tiles, 8x4 micro ============
__global__ __launch_bounds__(256) void av128(
    const float* __restrict__ P, const float* __restrict__ V, float* __restrict__ ctx)
{
    __shared__ float Ps[16][132];
    __shared__ float Vs[16][64];
    const int tid = threadIdx.x;
    const int tx = tid & 15, ty = tid >> 4;
    const int r  = tid >> 2;
    const int kq = (tid & 3) * 4;
    const int q0 = blockIdx.x * 128;
    const int bh = blockIdx.y;
    const int b = bh / Hv, h = bh % Hv;
    const size_t pbase = (size_t)bh * Sv * Sv;
    const size_t vbase = (size_t)bh * Sv * DHv;
    const int vrow = tid >> 4;          // 0..15
    const int vcol = (tid & 15) * 4;    // 0..60

    float acc[8][4];
#pragma unroll
    for (int i = 0; i < 8; ++i)
#pragma unroll
        for (int j = 0; j < 4; ++j) acc[i][j] = 0.f;

    for (int k0 = 0; k0 < Sv; k0 += 16) {
        float4 a0 = *reinterpret_cast<const float4*>(P + pbase + (size_t)(q0 + r) * Sv + k0 + kq);
        float4 a1 = *reinterpret_cast<const float4*>(P + pbase + (size_t)(q0 + r + 64) * Sv + k0 + kq);
        Ps[kq + 0][r] = a0.x; Ps[kq + 1][r] = a0.y; Ps[kq + 2][r] = a0.z; Ps[kq + 3][r] = a0.w;
        Ps[kq + 0][r + 64] = a1.x; Ps[kq + 1][r + 64] = a1.y;
        Ps[kq + 2][r + 64] = a1.z; Ps[kq + 3][r + 64] = a1.w;

        float4 vv = *reinterpret_cast<const float4*>(V + vbase + (size_t)(k0 + vrow) * DHv + vcol);
        *reinterpret_cast<float4*>(&Vs[vrow][vcol]) = vv;
        __syncthreads();

#pragma unroll
        for (int k = 0; k < 16; ++k) {
            float4 fa0 = *reinterpret_cast<const float4*>(&Ps[k][ty * 4]);
            float4 fa1 = *reinterpret_cast<const float4*>(&Ps[k][ty * 4 + 64]);
            float4 fb  = *reinterpret_cast<const float4*>(&Vs[k][tx * 4]);
            float a[8] = {fa0.x, fa0.y, fa0.z, fa0.w, fa1.x, fa1.y, fa1.z, fa1.w};
            float bq[4] = {fb.x, fb.y, fb.z, fb.w};
#pragma unroll
            for (int i = 0; i < 8; ++i)
#pragma unroll
                for (int j = 0; j < 4; ++j) acc[i][j] += a[i] * bq[j];
        }
        __syncthreads();
    }

#pragma unroll
    for (int qi = 0; qi < 2; ++qi) {
#pragma unroll
        for (int i = 0; i < 4; ++i) {
            int qrow = q0 + qi * 64 + ty * 4 + i;
            int ai = qi * 4 + i;
            float4 v = make_float4(acc[ai][0], acc[ai][1], acc[ai][2], acc[ai][3]);
            *reinterpret_cast<float4*>(ctx + ((size_t)b * Sv + qrow) * Dv + h * DHv + tx * 4) = v;
        }
    }
}

// ---------------- LayerNorm over last dim (768) -------------------------------
__global__ __launch_bounds__(256) void layernorm_row(
    const float* __restrict__ pre, const float* __restrict__ w,
    const float* __restrict__ bb, float* __restrict__ out)
{
    __shared__ float red[9];
    const int t = threadIdx.x;
    const size_t row = blockIdx.x;
    const float* x = pre + row * Dv;

    float v[3];
#pragma unroll
    for (int j = 0; j < 3; ++j) v[j] = x[t + 256 * j];
    float s = v[0] + v[1] + v[2];
    s = blockReduce256(s, false, red);
    float u = s * (1.f / 768.f);
    float d0 = v[0] - u, d1 = v[1] - u, d2 = v[2] - u;
    float sq = d0 * d0 + d1 * d1 + d2 * d2;
    sq = blockReduce256(sq, false, red);
    float var = sq * (1.f / 768.f);
    float rr = rsqrtf(var + 1e-12f);
    float dd[3] = {d0, d1, d2};
#pragma unroll
    for (int j = 0; j < 3; ++j) {
        int c = t + 256 * j;
        out[row * Dv + c] = dd[j] * rr * w[c] + bb[c];
    }
}

// ------------------------------------------------------------------------------
extern "C" void kernel_launch(void* const* d_in, const int* in_sizes, int n_in,
                              void* d_out, int out_size)
{
    const float* hidden = (const float*)d_in[0];
    const float* mask   = (const float*)d_in[1];
    const float* prev   = (const float*)d_in[2];
    const float* Wq = (const float*)d_in[3];
    const float* bq = (const float*)d_in[4];
    const float* Wk = (const float*)d_in[5];
    const float* bk = (const float*)d_in[6];
    const float* Wv = (const float*)d_in[7];
    const float* bv = (const float*)d_in[8];
    const float* cw = (const float*)d_in[9];
    const float* cb = (const float*)d_in[10];
    const float* Wo = (const float*)d_in[11];
    const float* bo = (const float*)d_in[12];
    const float* lnw = (const float*)d_in[13];
    const float* lnb = (const float*)d_in[14];
    float* out = (float*)d_out;

    float *q, *k, *v, *att, *ctx;
    cudaGetSymbolAddress((void**)&q,   g_q);
    cudaGetSymbolAddress((void**)&k,   g_k);
    cudaGetSymbolAddress((void**)&v,   g_v);
    cudaGetSymbolAddress((void**)&att, g_att);
    cudaGetSymbolAddress((void**)&ctx, g_ctx);

    // fused QKV projections: 6 x 32 x 3 = 576 CTAs
    gemm_qkv<<<dim3(Dv / 128, Mv / 128, 3), 256>>>(hidden, Wq, bq, Wk, bk, Wv, bv, q, k, v);

    qk128<<<dim3(Sv / 128, Sv / 128, BHv), 256>>>(q, k, att);

    mix_softmax<<<dim3(Sv, Bv), 256>>>(att, prev, mask, cw, cb);

    av128<<<dim3(Sv / 128, BHv), 256>>>(att, v, ctx);

    gemm_out<<<dim3(Dv / 128, Mv / 128), 256>>>(ctx, Wo, bo, hidden, q);

    layernorm_row<<<Mv, 256>>>(q, lnw, lnb, out);
}

// round 3
// speedup vs baseline: 2.1059x; 1.4541x over previous
#include <cuda_runtime.h>
#include <cstddef>

#define Bv 4
#define Sv 1024
#define Dv 768
#define Hv 12
#define DHv 64
#define Mv 4096   // B*S
#define BHv 48    // B*H

// ---------------- scratch (device globals; no allocation allowed) ------------
__device__ float g_q[Mv * Dv];              // also reused as pre-LN buffer
__device__ float g_k[Mv * Dv];
__device__ float g_v[Mv * Dv];
__device__ float g_ctx[Mv * Dv];
__device__ float g_att[(size_t)BHv * Sv * Sv];          // scores then probs (192 MB)
__device__ unsigned g_wt[4 * Dv * Dv];                  // Wq,Wk,Wv,Wo transposed, tf32 bits
__device__ unsigned g_vt[(size_t)BHv * DHv * Sv];       // V transposed per head, tf32 bits

// ---------------- helpers ----------------------------------------------------
__device__ __forceinline__ unsigned f2tf32(float x) {
    unsigned u;
    asm("cvt.rna.tf32.f32 %0, %1;" : "=r"(u) : "f"(x));
    return u;
}

__device__ __forceinline__ void mma_tf32(float c[4], const unsigned a[4], const unsigned b[2]) {
    asm volatile(
        "mma.sync.aligned.m16n8k8.row.col.f32.tf32.tf32.f32 "
        "{%0,%1,%2,%3}, {%4,%5,%6,%7}, {%8,%9}, {%0,%1,%2,%3};\n"
        : "+f"(c[0]), "+f"(c[1]), "+f"(c[2]), "+f"(c[3])
        : "r"(a[0]), "r"(a[1]), "r"(a[2]), "r"(a[3]), "r"(b[0]), "r"(b[1]));
}

__device__ __forceinline__ float blockReduce256(float v, bool domax, float* sh) {
    const int lane = threadIdx.x & 31;
    const int w = threadIdx.x >> 5;
#pragma unroll
    for (int o = 16; o > 0; o >>= 1) {
        float u = __shfl_xor_sync(0xffffffffu, v, o);
        v = domax ? fmaxf(v, u) : (v + u);
    }
    if (lane == 0) sh[w] = v;
    __syncthreads();
    if (w == 0) {
        float x = (lane < 8) ? sh[lane] : (domax ? -3.4e38f : 0.f);
#pragma unroll
        for (int o = 4; o > 0; o >>= 1) {
            float u = __shfl_xor_sync(0xffffffffu, x, o);
            x = domax ? fmaxf(x, u) : (x + u);
        }
        if (lane == 0) sh[8] = x;
    }
    __syncthreads();
    return sh[8];
}

// ---------------- once-per-launch transposes (to tf32 bits) ------------------
__global__ __launch_bounds__(256) void transpose_w4(
    const float* __restrict__ W0, const float* __restrict__ W1,
    const float* __restrict__ W2, const float* __restrict__ W3,
    unsigned* __restrict__ out)
{
    __shared__ float t[32][33];
    const float* W = (blockIdx.z == 0) ? W0 : (blockIdx.z == 1) ? W1
                   : (blockIdx.z == 2) ? W2 : W3;
    unsigned* O = out + (size_t)blockIdx.z * Dv * Dv;
    const int tx = threadIdx.x & 31, ty = threadIdx.x >> 5;
    const int k0 = blockIdx.x * 32, n0 = blockIdx.y * 32;
#pragma unroll
    for (int i = 0; i < 4; ++i)
        t[ty + 8 * i][tx] = W[(size_t)(k0 + ty + 8 * i) * Dv + n0 + tx];
    __syncthreads();
#pragma unroll
    for (int i = 0; i < 4; ++i)
        O[(size_t)(n0 + ty + 8 * i) * Dv + k0 + tx] = f2tf32(t[tx][ty + 8 * i]);
}

__global__ __launch_bounds__(256) void transpose_v(
    const float* __restrict__ V, unsigned* __restrict__ Vt)
{
    __shared__ float t[32][33];
    const int bh = blockIdx.z;
    const int s0 = blockIdx.x * 32, d0 = blockIdx.y * 32;
    const float* Vb = V + (size_t)bh * Sv * DHv;
    unsigned* Ob = Vt + (size_t)bh * DHv * Sv;
    const int tx = threadIdx.x & 31, ty = threadIdx.x >> 5;
#pragma unroll
    for (int i = 0; i < 4; ++i)
        t[ty + 8 * i][tx] = Vb[(size_t)(s0 + ty + 8 * i) * DHv + d0 + tx];
    __syncthreads();
#pragma unroll
    for (int i = 0; i < 4; ++i)
        Ob[(size_t)(d0 + ty + 8 * i) * Sv + s0 + tx] = f2tf32(t[tx][ty + 8 * i]);
}

// ============ tf32 MMA GEMM: 128x128 tile, A fp32 [M,K], Bt tf32 [N,K] =======
__device__ __forceinline__ void mma_gemm128(
    const float* __restrict__ A, const unsigned* __restrict__ Bt,
    const float* __restrict__ bias, const float* __restrict__ resid,
    float* __restrict__ out, int K, int N, int headLayout, int m0, int n0)
{
    __shared__ unsigned As[128][20];
    __shared__ unsigned Bs[128][20];
    const int tid = threadIdx.x, lane = tid & 31, warp = tid >> 5;
    const int wm = (warp >> 2) * 64, wn = (warp & 3) * 32;
    const int g = lane >> 2, q = lane & 3;

    float c[4][4][4];
#pragma unroll
    for (int mt = 0; mt < 4; ++mt)
#pragma unroll
        for (int nt = 0; nt < 4; ++nt)
#pragma unroll
            for (int i = 0; i < 4; ++i) c[mt][nt][i] = 0.f;

    for (int k0 = 0; k0 < K; k0 += 16) {
#pragma unroll
        for (int it = 0; it < 2; ++it) {
            int idx = tid + it * 256;
            int row = idx >> 2, col = (idx & 3) * 4;
            float4 a = *reinterpret_cast<const float4*>(A + (size_t)(m0 + row) * K + k0 + col);
            uint4 av;
            av.x = f2tf32(a.x); av.y = f2tf32(a.y); av.z = f2tf32(a.z); av.w = f2tf32(a.w);
            *reinterpret_cast<uint4*>(&As[row][col]) = av;
            uint4 bvv = *reinterpret_cast<const uint4*>(Bt + (size_t)(n0 + row) * K + k0 + col);
            *reinterpret_cast<uint4*>(&Bs[row][col]) = bvv;
        }
        __syncthreads();
#pragma unroll
        for (int kk = 0; kk < 16; kk += 8) {
            unsigned af[4][4], bf[4][2];
#pragma unroll
            for (int mt = 0; mt < 4; ++mt) {
                int r = wm + mt * 16 + g;
                af[mt][0] = As[r][kk + q];
                af[mt][1] = As[r + 8][kk + q];
                af[mt][2] = As[r][kk + q + 4];
                af[mt][3] = As[r + 8][kk + q + 4];
            }
#pragma unroll
            for (int nt = 0; nt < 4; ++nt) {
                int cn = wn + nt * 8 + g;
                bf[nt][0] = Bs[cn][kk + q];
                bf[nt][1] = Bs[cn][kk + q + 4];
            }
#pragma unroll
            for (int mt = 0; mt < 4; ++mt)
#pragma unroll
                for (int nt = 0; nt < 4; ++nt) mma_tf32(c[mt][nt], af[mt], bf[nt]);
        }
        __syncthreads();
    }

#pragma unroll
    for (int mt = 0; mt < 4; ++mt) {
#pragma unroll
        for (int i = 0; i < 2; ++i) {
            int row = m0 + wm + mt * 16 + g + 8 * i;
#pragma unroll
            for (int nt = 0; nt < 4; ++nt) {
                int col = n0 + wn + nt * 8 + 2 * q;
                float2 v;
                v.x = c[mt][nt][2 * i + 0];
                v.y = c[mt][nt][2 * i + 1];
                float2 bb = *reinterpret_cast<const float2*>(bias + col);
                v.x += bb.x; v.y += bb.y;
                if (resid) {
                    float2 rv = *reinterpret_cast<const float2*>(resid + (size_t)row * N + col);
                    v.x += rv.x; v.y += rv.y;
                }
                if (headLayout) {
                    int b = row >> 10, s = row & 1023;
                    int h = col >> 6, d = col & 63;
                    *reinterpret_cast<float2*>(out + ((size_t)(b * Hv + h) * Sv + s) * DHv + d) = v;
                } else {
                    *reinterpret_cast<float2*>(out + (size_t)row * N + col) = v;
                }
            }
        }
    }
}

// fused Q/K/V projection
__global__ __launch_bounds__(256) void gemm_qkv(
    const float* __restrict__ A, const unsigned* __restrict__ Wt,
    const float* __restrict__ bq, const float* __restrict__ bk, const float* __restrict__ bvb,
    float* __restrict__ q, float* __restrict__ k, float* __restrict__ v)
{
    const unsigned* Bt = Wt + (size_t)blockIdx.z * Dv * Dv;
    const float* bb = (blockIdx.z == 0) ? bq : (blockIdx.z == 1) ? bk : bvb;
    float* o = (blockIdx.z == 0) ? q : (blockIdx.z == 1) ? k : v;
    mma_gemm128(A, Bt, bb, nullptr, o, Dv, Dv, 1, blockIdx.y * 128, blockIdx.x * 128);
}

__global__ __launch_bounds__(256) void gemm_out(
    const float* __restrict__ A, const unsigned* __restrict__ Wt,
    const float* __restrict__ bias, const float* __restrict__ resid,
    float* __restrict__ out)
{
    mma_gemm128(A, Wt, bias, resid, out, Dv, Dv, 0, blockIdx.y * 128, blockIdx.x * 128);
}

// ============ scores = Q @ K^T / 8, per (b,h), tf32 MMA ======================
__global__ __launch_bounds__(256) void qk_mma(
    const float* __restrict__ Q, const float* __restrict__ Km, float* __restrict__ att)
{
    __shared__ unsigned As[128][20];
    __shared__ unsigned Bs[128][20];
    const int tid = threadIdx.x, lane = tid & 31, warp = tid >> 5;
    const int wm = (warp >> 2) * 64, wn = (warp & 3) * 32;
    const int g = lane >> 2, q = lane & 3;
    const int n0 = blockIdx.x * 128, m0 = blockIdx.y * 128;
    const size_t base = (size_t)blockIdx.z * Sv * DHv;

    float c[4][4][4];
#pragma unroll
    for (int mt = 0; mt < 4; ++mt)
#pragma unroll
        for (int nt = 0; nt < 4; ++nt)
#pragma unroll
            for (int i = 0; i < 4; ++i) c[mt][nt][i] = 0.f;

#pragma unroll
    for (int k0 = 0; k0 < DHv; k0 += 16) {
#pragma unroll
        for (int it = 0; it < 2; ++it) {
            int idx = tid + it * 256;
            int row = idx >> 2, col = (idx & 3) * 4;
            float4 a = *reinterpret_cast<const float4*>(Q + base + (size_t)(m0 + row) * DHv + k0 + col);
            uint4 av;
            av.x = f2tf32(a.x); av.y = f2tf32(a.y); av.z = f2tf32(a.z); av.w = f2tf32(a.w);
            *reinterpret_cast<uint4*>(&As[row][col]) = av;
            float4 b = *reinterpret_cast<const float4*>(Km + base + (size_t)(n0 + row) * DHv + k0 + col);
            uint4 bb;
            bb.x = f2tf32(b.x); bb.y = f2tf32(b.y); bb.z = f2tf32(b.z); bb.w = f2tf32(b.w);
            *reinterpret_cast<uint4*>(&Bs[row][col]) = bb;
        }
        __syncthreads();
#pragma unroll
        for (int kk = 0; kk < 16; kk += 8) {
            unsigned af[4][4], bf[4][2];
#pragma unroll
            for (int mt = 0; mt < 4; ++mt) {
                int r = wm + mt * 16 + g;
                af[mt][0] = As[r][kk + q];
                af[mt][1] = As[r + 8][kk + q];
                af[mt][2] = As[r][kk + q + 4];
                af[mt][3] = As[r + 8][kk + q + 4];
            }
#pragma unroll
            for (int nt = 0; nt < 4; ++nt) {
                int cn = wn + nt * 8 + g;
                bf[nt][0] = Bs[cn][kk + q];
                bf[nt][1] = Bs[cn][kk + q + 4];
            }
#pragma unroll
            for (int mt = 0; mt < 4; ++mt)
#pragma unroll
                for (int nt = 0; nt < 4; ++nt) mma_tf32(c[mt][nt], af[mt], bf[nt]);
        }
        __syncthreads();
    }

    const size_t ab = (size_t)blockIdx.z * Sv * Sv;
#pragma unroll
    for (int mt = 0; mt < 4; ++mt) {
#pragma unroll
        for (int i = 0; i < 2; ++i) {
            int row = m0 + wm + mt * 16 + g + 8 * i;
#pragma unroll
            for (int nt = 0; nt < 4; ++nt) {
                int col = n0 + wn + nt * 8 + 2 * q;
                float2 v;
                v.x = c[mt][nt][2 * i + 0] * 0.125f;
                v.y = c[mt][nt][2 * i + 1] * 0.125f;
                *reinterpret_cast<float2*>(att + ab + (size_t)row * Sv + col) = v;
            }
        }
    }
}

// ---- softmax(scores+mask) -> mix with conv(prev) -> softmax again (in place)
__global__ __launch_bounds__(256) void mix_softmax(
    float* __restrict__ att, const float* __restrict__ prev,
    const float* __restrict__ mask, const float* __restrict__ cw_g,
    const float* __restrict__ cb_g)
{
    __shared__ float cw[144];
    __shared__ float cb[12];
    __shared__ float red[9];
    const int t = threadIdx.x;
    const int qi = blockIdx.x;
    const int b = blockIdx.y;
    if (t < 144) cw[t] = cw_g[t];
    if (t < 12) cb[t] = cb_g[t];
    __syncthreads();

    float pv[12][4];
#pragma unroll
    for (int i = 0; i < 12; ++i) {
        float4 p4 = *reinterpret_cast<const float4*>(
            prev + ((size_t)(b * Hv + i) * Sv + qi) * Sv + 4 * t);
        pv[i][0] = p4.x; pv[i][1] = p4.y; pv[i][2] = p4.z; pv[i][3] = p4.w;
    }
#pragma unroll
    for (int j = 0; j < 4; ++j) {
        float tmp[12];
#pragma unroll
        for (int o = 0; o < 12; ++o) {
            float a = cb[o];
#pragma unroll
            for (int i = 0; i < 12; ++i) a += cw[o * 12 + i] * pv[i][j];
            tmp[o] = a;
        }
#pragma unroll
        for (int o = 0; o < 12; ++o) pv[o][j] = tmp[o];
    }

    float4 m4 = *reinterpret_cast<const float4*>(mask + (size_t)b * Sv + 4 * t);
    float mk[4] = {m4.x, m4.y, m4.z, m4.w};

#pragma unroll
    for (int o = 0; o < 12; ++o) {
        const size_t rb = ((size_t)(b * Hv + o) * Sv + qi) * Sv + 4 * t;
        float4 s4 = *reinterpret_cast<const float4*>(att + rb);
        float s[4] = {s4.x + mk[0], s4.y + mk[1], s4.z + mk[2], s4.w + mk[3]};

        float mx = fmaxf(fmaxf(s[0], s[1]), fmaxf(s[2], s[3]));
        mx = blockReduce256(mx, true, red);
        float e[4], ls = 0.f;
#pragma unroll
        for (int j = 0; j < 4; ++j) { e[j] = __expf(s[j] - mx); ls += e[j]; }
        float sum1 = blockReduce256(ls, false, red);
        float inv1 = 1.f / sum1;

        float mixd[4];
#pragma unroll
        for (int j = 0; j < 4; ++j) mixd[j] = 0.5f * pv[o][j] + 0.5f * (e[j] * inv1);

        float mx2 = fmaxf(fmaxf(mixd[0], mixd[1]), fmaxf(mixd[2], mixd[3]));
        mx2 = blockReduce256(mx2, true, red);
        float e2[4], ls2 = 0.f;
#pragma unroll
        for (int j = 0; j < 4; ++j) { e2[j] = __expf(mixd[j] - mx2); ls2 += e2[j]; }
        float sum2 = blockReduce256(ls2, false, red);
        float inv2 = 1.f / sum2;
        float4 o4 = make_float4(e2[0] * inv2, e2[1] * inv2, e2[2] * inv2, e2[3] * inv2);
        *reinterpret_cast<float4*>(att + rb) = o4;
    }
}

// ============ ctx = probs @ V, per (b,h), tf32 MMA, 128x64 tile ==============
__global__ __launch_bounds__(256) void av_mma(
    const float* __restrict__ P, const unsigned* __restrict__ Vt, float* __restrict__ ctx)
{
    __shared__ unsigned As[128][20];
    __shared__ unsigned Bs[64][20];
    const int tid = threadIdx.x, lane = tid & 31, warp = tid >> 5;
    const int wm = (warp >> 2) * 64, wn = (warp & 3) * 16;
    const int g = lane >> 2, q = lane & 3;
    const int q0 = blockIdx.x * 128;
    const int bh = blockIdx.y;
    const int b = bh / Hv, h = bh % Hv;
    const size_t pbase = (size_t)bh * Sv * Sv;
    const size_t vtb = (size_t)bh * DHv * Sv;

    float c[4][2][4];
#pragma unroll
    for (int mt = 0; mt < 4; ++mt)
#pragma unroll
        for (int nt = 0; nt < 2; ++nt)
#pragma unroll
            for (int i = 0; i < 4; ++i) c[mt][nt][i] = 0.f;

    for (int k0 = 0; k0 < Sv; k0 += 16) {
#pragma unroll
        for (int it = 0; it < 2; ++it) {
            int idx = tid + it * 256;
            int row = idx >> 2, col = (idx & 3) * 4;
            float4 a = *reinterpret_cast<const float4*>(P + pbase + (size_t)(q0 + row) * Sv + k0 + col);
            uint4 av;
            av.x = f2tf32(a.x); av.y = f2tf32(a.y); av.z = f2tf32(a.z); av.w = f2tf32(a.w);
            *reinterpret_cast<uint4*>(&As[row][col]) = av;
        }
        {
            int row = tid >> 2, col = (tid & 3) * 4;
            uint4 bv = *reinterpret_cast<const uint4*>(Vt + vtb + (size_t)row * Sv + k0 + col);
            *reinterpret_cast<uint4*>(&Bs[row][col]) = bv;
        }
        __syncthreads();
#pragma unroll
        for (int kk = 0; kk < 16; kk += 8) {
            unsigned af[4][4], bf[2][2];
#pragma unroll
            for (int mt = 0; mt < 4; ++mt) {
                int r = wm + mt * 16 + g;
                af[mt][0] = As[r][kk + q];
                af[mt][1] = As[r + 8][kk + q];
                af[mt][2] = As[r][kk + q + 4];
                af[mt][3] = As[r + 8][kk + q + 4];
            }
#pragma unroll
            for (int nt = 0; nt < 2; ++nt) {
                int cn = wn + nt * 8 + g;
                bf[nt][0] = Bs[cn][kk + q];
                bf[nt][1] = Bs[cn][kk + q + 4];
            }
#pragma unroll
            for (int mt = 0; mt < 4; ++mt)
#pragma unroll
                for (int nt = 0; nt < 2; ++nt) mma_tf32(c[mt][nt], af[mt], bf[nt]);
        }
        __syncthreads();
    }

#pragma unroll
    for (int mt = 0; mt < 4; ++mt) {
#pragma unroll
        for (int i = 0; i < 2; ++i) {
            int row = q0 + wm + mt * 16 + g + 8 * i;
#pragma unroll
            for (int nt = 0; nt < 2; ++nt) {
                int col = wn + nt * 8 + 2 * q;  // dh index
                float2 v;
                v.x = c[mt][nt][2 * i + 0];
                v.y = c[mt][nt][2 * i + 1];
                *reinterpret_cast<float2*>(ctx + ((size_t)b * Sv + row) * Dv + h * DHv + col) = v;
            }
        }
    }
}

// ---------------- LayerNorm over last dim (768) -------------------------------
__global__ __launch_bounds__(256) void layernorm_row(
    const float* __restrict__ pre, const float* __restrict__ w,
    const float* __restrict__ bb, float* __restrict__ out)
{
    __shared__ float red[9];
    const int t = threadIdx.x;
    const size_t row = blockIdx.x;
    const float* x = pre + row * Dv;

    float v[3];
#pragma unroll
    for (int j = 0; j < 3; ++j) v[j] = x[t + 256 * j];
    float s = v[0] + v[1] + v[2];
    s = blockReduce256(s, false, red);
    float u = s * (1.f / 768.f);
    float d0 = v[0] - u, d1 = v[1] - u, d2 = v[2] - u;
    float sq = d0 * d0 + d1 * d1 + d2 * d2;
    sq = blockReduce256(sq, false, red);
    float var = sq * (1.f / 768.f);
    float rr = rsqrtf(var + 1e-12f);
    float dd[3] = {d0, d1, d2};
#pragma unroll
    for (int j = 0; j < 3; ++j) {
        int ci = t + 256 * j;
        out[row * Dv + ci] = dd[j] * rr * w[ci] + bb[ci];
    }
}

// ------------------------------------------------------------------------------
extern "C" void kernel_launch(void* const* d_in, const int* in_sizes, int n_in,
                              void* d_out, int out_size)
{
    const float* hidden = (const float*)d_in[0];
    const float* mask   = (const float*)d_in[1];
    const float* prev   = (const float*)d_in[2];
    const float* Wq = (const float*)d_in[3];
    const float* bq = (const float*)d_in[4];
    const float* Wk = (const float*)d_in[5];
    const float* bk = (const float*)d_in[6];
    const float* Wv = (const float*)d_in[7];
    const float* bvp = (const float*)d_in[8];
    const float* cw = (const float*)d_in[9];
    const float* cb = (const float*)d_in[10];
    const float* Wo = (const float*)d_in[11];
    const float* bo = (const float*)d_in[12];
    const float* lnw = (const float*)d_in[13];
    const float* lnb = (const float*)d_in[14];
    float* out = (float*)d_out;

    float *q, *k, *v, *att, *ctx;
    unsigned *wt, *vt;
    cudaGetSymbolAddress((void**)&q,   g_q);
    cudaGetSymbolAddress((void**)&k,   g_k);
    cudaGetSymbolAddress((void**)&v,   g_v);
    cudaGetSymbolAddress((void**)&att, g_att);
    cudaGetSymbolAddress((void**)&ctx, g_ctx);
    cudaGetSymbolAddress((void**)&wt,  g_wt);
    cudaGetSymbolAddress((void**)&vt,  g_vt);

    // pre-transpose weights to [N][K] tf32 (cheap, once per launch)
    transpose_w4<<<dim3(24, 24, 4), 256>>>(Wq, Wk, Wv, Wo, wt);

    // fused QKV projections (tensor core)
    gemm_qkv<<<dim3(Dv / 128, Mv / 128, 3), 256>>>(hidden, wt, bq, bk, bvp, q, k, v);

    // V -> [bh][dh][s] tf32
    transpose_v<<<dim3(Sv / 32, DHv / 32, BHv), 256>>>(v, vt);

    qk_mma<<<dim3(Sv / 128, Sv / 128, BHv), 256>>>(q, k, att);

    mix_softmax<<<dim3(Sv, Bv), 256>>>(att, prev, mask, cw, cb);

    av_mma<<<dim3(Sv / 128, BHv), 256>>>(att, vt, ctx);

    gemm_out<<<dim3(Dv / 128, Mv / 128), 256>>>(ctx, wt + 3 * Dv * Dv, bo, hidden, q);

    layernorm_row<<<Mv, 256>>>(q, lnw, lnb, out);
}

// round 4
// speedup vs baseline: 2.9641x; 1.4075x over previous
#include <cuda_runtime.h>
#include <cuda_fp16.h>
#include <cstddef>

#define Bv 4
#define Sv 1024
#define Dv 768
#define Hv 12
#define DHv 64
#define Mv 4096   // B*S
#define BHv 48    // B*H

// ---------------- scratch (device globals; no allocation allowed) ------------
__device__ float g_q[Mv * Dv];              // also reused as pre-LN buffer
__device__ float g_k[Mv * Dv];
__device__ float g_v[Mv * Dv];
__device__ float g_ctx[Mv * Dv];
__device__ __half g_att[(size_t)BHv * Sv * Sv];       // e1 then probs2 (96 MB fp16)
__device__ unsigned g_wt[4 * Dv * Dv];                // Wq,Wk,Wv,Wo transposed tf32
__device__ __half g_vt[(size_t)BHv * DHv * Sv];       // V transposed per head, fp16
__device__ float g_psum[(size_t)BHv * Sv * 8];        // per-CTA row-sum partials
__device__ float g_inv1[(size_t)BHv * Sv];            // 1/sum1 per row

// ---------------- helpers ----------------------------------------------------
__device__ __forceinline__ unsigned f2tf32(float x) {
    unsigned u;
    asm("cvt.rna.tf32.f32 %0, %1;" : "=r"(u) : "f"(x));
    return u;
}

__device__ __forceinline__ void mma_tf32(float c[4], const unsigned a[4], const unsigned b[2]) {
    asm volatile(
        "mma.sync.aligned.m16n8k8.row.col.f32.tf32.tf32.f32 "
        "{%0,%1,%2,%3}, {%4,%5,%6,%7}, {%8,%9}, {%0,%1,%2,%3};\n"
        : "+f"(c[0]), "+f"(c[1]), "+f"(c[2]), "+f"(c[3])
        : "r"(a[0]), "r"(a[1]), "r"(a[2]), "r"(a[3]), "r"(b[0]), "r"(b[1]));
}

__device__ __forceinline__ void mma_f16(float c[4], const unsigned a[4], const unsigned b[2]) {
    asm volatile(
        "mma.sync.aligned.m16n8k16.row.col.f32.f16.f16.f32 "
        "{%0,%1,%2,%3}, {%4,%5,%6,%7}, {%8,%9}, {%0,%1,%2,%3};\n"
        : "+f"(c[0]), "+f"(c[1]), "+f"(c[2]), "+f"(c[3])
        : "r"(a[0]), "r"(a[1]), "r"(a[2]), "r"(a[3]), "r"(b[0]), "r"(b[1]));
}

__device__ __forceinline__ float blockReduce256(float v, bool domax, float* sh) {
    const int lane = threadIdx.x & 31;
    const int w = threadIdx.x >> 5;
#pragma unroll
    for (int o = 16; o > 0; o >>= 1) {
        float u = __shfl_xor_sync(0xffffffffu, v, o);
        v = domax ? fmaxf(v, u) : (v + u);
    }
    if (lane == 0) sh[w] = v;
    __syncthreads();
    if (w == 0) {
        float x = (lane < 8) ? sh[lane] : (domax ? -3.4e38f : 0.f);
#pragma unroll
        for (int o = 4; o > 0; o >>= 1) {
            float u = __shfl_xor_sync(0xffffffffu, x, o);
            x = domax ? fmaxf(x, u) : (x + u);
        }
        if (lane == 0) sh[8] = x;
    }
    __syncthreads();
    return sh[8];
}

// ---------------- once-per-launch transposes ---------------------------------
__global__ __launch_bounds__(256) void transpose_w4(
    const float* __restrict__ W0, const float* __restrict__ W1,
    const float* __restrict__ W2, const float* __restrict__ W3,
    unsigned* __restrict__ out)
{
    __shared__ float t[32][33];
    const float* W = (blockIdx.z == 0) ? W0 : (blockIdx.z == 1) ? W1
                   : (blockIdx.z == 2) ? W2 : W3;
    unsigned* O = out + (size_t)blockIdx.z * Dv * Dv;
    const int tx = threadIdx.x & 31, ty = threadIdx.x >> 5;
    const int k0 = blockIdx.x * 32, n0 = blockIdx.y * 32;
#pragma unroll
    for (int i = 0; i < 4; ++i)
        t[ty + 8 * i][tx] = W[(size_t)(k0 + ty + 8 * i) * Dv + n0 + tx];
    __syncthreads();
#pragma unroll
    for (int i = 0; i < 4; ++i)
        O[(size_t)(n0 + ty + 8 * i) * Dv + k0 + tx] = f2tf32(t[tx][ty + 8 * i]);
}

__global__ __launch_bounds__(256) void transpose_v_h(
    const float* __restrict__ V, __half* __restrict__ Vt)
{
    __shared__ float t[32][33];
    const int bh = blockIdx.z;
    const int s0 = blockIdx.x * 32, d0 = blockIdx.y * 32;
    const float* Vb = V + (size_t)bh * Sv * DHv;
    __half* Ob = Vt + (size_t)bh * DHv * Sv;
    const int tx = threadIdx.x & 31, ty = threadIdx.x >> 5;
#pragma unroll
    for (int i = 0; i < 4; ++i)
        t[ty + 8 * i][tx] = Vb[(size_t)(s0 + ty + 8 * i) * DHv + d0 + tx];
    __syncthreads();
#pragma unroll
    for (int i = 0; i < 4; ++i)
        Ob[(size_t)(d0 + ty + 8 * i) * Sv + s0 + tx] = __float2half_rn(t[tx][ty + 8 * i]);
}

// ============ tf32 MMA GEMM: 128x128 tile, A fp32 [M,K], Bt tf32 [N,K] =======
__device__ __forceinline__ void mma_gemm128(
    const float* __restrict__ A, const unsigned* __restrict__ Bt,
    const float* __restrict__ bias, const float* __restrict__ resid,
    float* __restrict__ out, int K, int N, int headLayout, int m0, int n0)
{
    __shared__ unsigned As[128][20];
    __shared__ unsigned Bs[128][20];
    const int tid = threadIdx.x, lane = tid & 31, warp = tid >> 5;
    const int wm = (warp >> 2) * 64, wn = (warp & 3) * 32;
    const int g = lane >> 2, q = lane & 3;

    float c[4][4][4];
#pragma unroll
    for (int mt = 0; mt < 4; ++mt)
#pragma unroll
        for (int nt = 0; nt < 4; ++nt)
#pragma unroll
            for (int i = 0; i < 4; ++i) c[mt][nt][i] = 0.f;

    for (int k0 = 0; k0 < K; k0 += 16) {
#pragma unroll
        for (int it = 0; it < 2; ++it) {
            int idx = tid + it * 256;
            int row = idx >> 2, col = (idx & 3) * 4;
            float4 a = *reinterpret_cast<const float4*>(A + (size_t)(m0 + row) * K + k0 + col);
            uint4 av;
            av.x = f2tf32(a.x); av.y = f2tf32(a.y); av.z = f2tf32(a.z); av.w = f2tf32(a.w);
            *reinterpret_cast<uint4*>(&As[row][col]) = av;
            uint4 bvv = *reinterpret_cast<const uint4*>(Bt + (size_t)(n0 + row) * K + k0 + col);
            *reinterpret_cast<uint4*>(&Bs[row][col]) = bvv;
        }
        __syncthreads();
#pragma unroll
        for (int kk = 0; kk < 16; kk += 8) {
            unsigned af[4][4], bf[4][2];
#pragma unroll
            for (int mt = 0; mt < 4; ++mt) {
                int r = wm + mt * 16 + g;
                af[mt][0] = As[r][kk + q];
                af[mt][1] = As[r + 8][kk + q];
                af[mt][2] = As[r][kk + q + 4];
                af[mt][3] = As[r + 8][kk + q + 4];
            }
#pragma unroll
            for (int nt = 0; nt < 4; ++nt) {
                int cn = wn + nt * 8 + g;
                bf[nt][0] = Bs[cn][kk + q];
                bf[nt][1] = Bs[cn][kk + q + 4];
            }
#pragma unroll
            for (int mt = 0; mt < 4; ++mt)
#pragma unroll
                for (int nt = 0; nt < 4; ++nt) mma_tf32(c[mt][nt], af[mt], bf[nt]);
        }
        __syncthreads();
    }

#pragma unroll
    for (int mt = 0; mt < 4; ++mt) {
#pragma unroll
        for (int i = 0; i < 2; ++i) {
            int row = m0 + wm + mt * 16 + g + 8 * i;
#pragma unroll
            for (int nt = 0; nt < 4; ++nt) {
                int col = n0 + wn + nt * 8 + 2 * q;
                float2 v;
                v.x = c[mt][nt][2 * i + 0];
                v.y = c[mt][nt][2 * i + 1];
                float2 bb = *reinterpret_cast<const float2*>(bias + col);
                v.x += bb.x; v.y += bb.y;
                if (resid) {
                    float2 rv = *reinterpret_cast<const float2*>(resid + (size_t)row * N + col);
                    v.x += rv.x; v.y += rv.y;
                }
                if (headLayout) {
                    int b = row >> 10, s = row & 1023;
                    int h = col >> 6, d = col & 63;
                    *reinterpret_cast<float2*>(out + ((size_t)(b * Hv + h) * Sv + s) * DHv + d) = v;
                } else {
                    *reinterpret_cast<float2*>(out + (size_t)row * N + col) = v;
                }
            }
        }
    }
}

__global__ __launch_bounds__(256) void gemm_qkv(
    const float* __restrict__ A, const unsigned* __restrict__ Wt,
    const float* __restrict__ bq, const float* __restrict__ bk, const float* __restrict__ bvb,
    float* __restrict__ q, float* __restrict__ k, float* __restrict__ v)
{
    const unsigned* Bt = Wt + (size_t)blockIdx.z * Dv * Dv;
    const float* bb = (blockIdx.z == 0) ? bq : (blockIdx.z == 1) ? bk : bvb;
    float* o = (blockIdx.z == 0) ? q : (blockIdx.z == 1) ? k : v;
    mma_gemm128(A, Bt, bb, nullptr, o, Dv, Dv, 1, blockIdx.y * 128, blockIdx.x * 128);
}

__global__ __launch_bounds__(256) void gemm_out(
    const float* __restrict__ A, const unsigned* __restrict__ Wt,
    const float* __restrict__ bias, const float* __restrict__ resid,
    float* __restrict__ out)
{
    mma_gemm128(A, Wt, bias, resid, out, Dv, Dv, 0, blockIdx.y * 128, blockIdx.x * 128);
}

// ====== qk + exp epilogue: e1 = exp(s/8 + mask), fp16 store, row partials ====
__global__ __launch_bounds__(256) void qk_exp(
    const float* __restrict__ Q, const float* __restrict__ Km,
    const float* __restrict__ mask, __half* __restrict__ att,
    float* __restrict__ psum)
{
    __shared__ unsigned As[128][20];
    __shared__ unsigned Bs[128][20];
    __shared__ float sm_mask[128];
    __shared__ float sm_rs[128][4];
    const int tid = threadIdx.x, lane = tid & 31, warp = tid >> 5;
    const int wm = (warp >> 2) * 64, wn = (warp & 3) * 32;
    const int g = lane >> 2, q = lane & 3;
    const int n0 = blockIdx.x * 128, m0 = blockIdx.y * 128;
    const int bh = blockIdx.z, bb = bh / Hv;
    const size_t base = (size_t)bh * Sv * DHv;

    if (tid < 128) sm_mask[tid] = mask[(size_t)bb * Sv + n0 + tid];

    float c[4][4][4];
#pragma unroll
    for (int mt = 0; mt < 4; ++mt)
#pragma unroll
        for (int nt = 0; nt < 4; ++nt)
#pragma unroll
            for (int i = 0; i < 4; ++i) c[mt][nt][i] = 0.f;

#pragma unroll
    for (int k0 = 0; k0 < DHv; k0 += 16) {
#pragma unroll
        for (int it = 0; it < 2; ++it) {
            int idx = tid + it * 256;
            int row = idx >> 2, col = (idx & 3) * 4;
            float4 a = *reinterpret_cast<const float4*>(Q + base + (size_t)(m0 + row) * DHv + k0 + col);
            uint4 av;
            av.x = f2tf32(a.x); av.y = f2tf32(a.y); av.z = f2tf32(a.z); av.w = f2tf32(a.w);
            *reinterpret_cast<uint4*>(&As[row][col]) = av;
            float4 b = *reinterpret_cast<const float4*>(Km + base + (size_t)(n0 + row) * DHv + k0 + col);
            uint4 bv;
            bv.x = f2tf32(b.x); bv.y = f2tf32(b.y); bv.z = f2tf32(b.z); bv.w = f2tf32(b.w);
            *reinterpret_cast<uint4*>(&Bs[row][col]) = bv;
        }
        __syncthreads();
#pragma unroll
        for (int kk = 0; kk < 16; kk += 8) {
            unsigned af[4][4], bf[4][2];
#pragma unroll
            for (int mt = 0; mt < 4; ++mt) {
                int r = wm + mt * 16 + g;
                af[mt][0] = As[r][kk + q];
                af[mt][1] = As[r + 8][kk + q];
                af[mt][2] = As[r][kk + q + 4];
                af[mt][3] = As[r + 8][kk + q + 4];
            }
#pragma unroll
            for (int nt = 0; nt < 4; ++nt) {
                int cn = wn + nt * 8 + g;
                bf[nt][0] = Bs[cn][kk + q];
                bf[nt][1] = Bs[cn][kk + q + 4];
            }
#pragma unroll
            for (int mt = 0; mt < 4; ++mt)
#pragma unroll
                for (int nt = 0; nt < 4; ++nt) mma_tf32(c[mt][nt], af[mt], bf[nt]);
        }
        __syncthreads();
    }

    const size_t ab = (size_t)bh * Sv * Sv;
    float rsum[4][2];
#pragma unroll
    for (int mt = 0; mt < 4; ++mt) {
#pragma unroll
        for (int i = 0; i < 2; ++i) {
            rsum[mt][i] = 0.f;
            int row = m0 + wm + mt * 16 + g + 8 * i;
#pragma unroll
            for (int nt = 0; nt < 4; ++nt) {
                int lcol = wn + nt * 8 + 2 * q;
                float e0 = __expf(c[mt][nt][2 * i + 0] * 0.125f + sm_mask[lcol]);
                float e1 = __expf(c[mt][nt][2 * i + 1] * 0.125f + sm_mask[lcol + 1]);
                rsum[mt][i] += e0 + e1;
                *reinterpret_cast<__half2*>(att + ab + (size_t)row * Sv + n0 + lcol) =
                    __floats2half2_rn(e0, e1);
            }
        }
    }
    // reduce partial row sums: over q lanes, then across the 4 n-warps
#pragma unroll
    for (int mt = 0; mt < 4; ++mt)
#pragma unroll
        for (int i = 0; i < 2; ++i) {
            float r = rsum[mt][i];
            r += __shfl_xor_sync(0xffffffffu, r, 1);
            r += __shfl_xor_sync(0xffffffffu, r, 2);
            if ((lane & 3) == 0) sm_rs[wm + mt * 16 + g + 8 * i][warp & 3] = r;
        }
    __syncthreads();
    if (tid < 128) {
        float s = (sm_rs[tid][0] + sm_rs[tid][1]) + (sm_rs[tid][2] + sm_rs[tid][3]);
        psum[((size_t)bh * Sv + m0 + tid) * 8 + blockIdx.x] = s;
    }
}

// ---------------- combine partials -> inv_sum1 --------------------------------
__global__ __launch_bounds__(256) void stats_combine(
    const float* __restrict__ psum, float* __restrict__ inv1)
{
    int i = blockIdx.x * 256 + threadIdx.x;
    const float* p = psum + (size_t)i * 8;
    float s = ((p[0] + p[1]) + (p[2] + p[3])) + ((p[4] + p[5]) + (p[6] + p[7]));
    inv1[i] = 1.f / s;
}

// ---- mix: p = e1*inv1; mixed = .5*conv(prev)+.5*p; p2 = softmax2 (fp16 io) ----
__global__ __launch_bounds__(256) void mix2(
    __half* __restrict__ att, const float* __restrict__ prev,
    const float* __restrict__ inv1g, const float* __restrict__ cw_g,
    const float* __restrict__ cb_g)
{
    __shared__ float cw[144];
    __shared__ float cb[12];
    __shared__ float red[9];
    const int t = threadIdx.x;
    const int qi = blockIdx.x;
    const int b = blockIdx.y;
    if (t < 144) cw[t] = cw_g[t];
    if (t < 12) cb[t] = cb_g[t];
    __syncthreads();

    // p (softmax1 probs) for all 12 heads at this (b, qi) row, 4 cols/thread
    float pv[12][4];
#pragma unroll
    for (int i = 0; i < 12; ++i) {
        const __half2* pa = reinterpret_cast<const __half2*>(
            att + ((size_t)(b * Hv + i) * Sv + qi) * Sv + 4 * t);
        __half2 h0 = pa[0], h1 = pa[1];
        float inv = inv1g[(size_t)(b * Hv + i) * Sv + qi];
        pv[i][0] = __low2float(h0) * inv;  pv[i][1] = __high2float(h0) * inv;
        pv[i][2] = __low2float(h1) * inv;  pv[i][3] = __high2float(h1) * inv;
    }
    // prev + 1x1 conv over heads
    float pr[12][4];
#pragma unroll
    for (int i = 0; i < 12; ++i) {
        float4 p4 = *reinterpret_cast<const float4*>(
            prev + ((size_t)(b * Hv + i) * Sv + qi) * Sv + 4 * t);
        pr[i][0] = p4.x; pr[i][1] = p4.y; pr[i][2] = p4.z; pr[i][3] = p4.w;
    }

#pragma unroll
    for (int o = 0; o < 12; ++o) {
        float e2[4], ls = 0.f;
#pragma unroll
        for (int j = 0; j < 4; ++j) {
            float a = cb[o];
#pragma unroll
            for (int i = 0; i < 12; ++i) a += cw[o * 12 + i] * pr[i][j];
            float mixd = 0.5f * a + 0.5f * pv[o][j];
            e2[j] = __expf(mixd);
            ls += e2[j];
        }
        float sum2 = blockReduce256(ls, false, red);
        float inv2 = 1.f / sum2;
        __half2* oa = reinterpret_cast<__half2*>(
            att + ((size_t)(b * Hv + o) * Sv + qi) * Sv + 4 * t);
        oa[0] = __floats2half2_rn(e2[0] * inv2, e2[1] * inv2);
        oa[1] = __floats2half2_rn(e2[2] * inv2, e2[3] * inv2);
    }
}

// ============ ctx = probs @ V, fp16 MMA m16n8k16, 128x64 tile ================
__global__ __launch_bounds__(256) void av_f16(
    const __half* __restrict__ P, const __half* __restrict__ Vt, float* __restrict__ ctx)
{
    __shared__ __half As[128][40];
    __shared__ __half Bs[64][40];
    const int tid = threadIdx.x, lane = tid & 31, warp = tid >> 5;
    const int wm = (warp >> 2) * 64, wn = (warp & 3) * 16;
    const int g = lane >> 2, qd = lane & 3;
    const int q0 = blockIdx.x * 128;
    const int bh = blockIdx.y;
    const int b = bh / Hv, h = bh % Hv;
    const __half* A = P + (size_t)bh * Sv * Sv;
    const __half* Vb = Vt + (size_t)bh * DHv * Sv;

    float c[4][2][4];
#pragma unroll
    for (int mt = 0; mt < 4; ++mt)
#pragma unroll
        for (int nt = 0; nt < 2; ++nt)
#pragma unroll
            for (int i = 0; i < 4; ++i) c[mt][nt][i] = 0.f;

    for (int k0 = 0; k0 < Sv; k0 += 32) {
#pragma unroll
        for (int it = 0; it < 2; ++it) {
            int idx = tid + it * 256;
            int row = idx >> 2, c8 = (idx & 3) * 8;
            uint4 v = *reinterpret_cast<const uint4*>(A + (size_t)(q0 + row) * Sv + k0 + c8);
            *reinterpret_cast<uint4*>(&As[row][c8]) = v;
        }
        {
            int row = tid >> 2, c8 = (tid & 3) * 8;
            uint4 v = *reinterpret_cast<const uint4*>(Vb + (size_t)row * Sv + k0 + c8);
            *reinterpret_cast<uint4*>(&Bs[row][c8]) = v;
        }
        __syncthreads();
#pragma unroll
        for (int kk = 0; kk < 32; kk += 16) {
            unsigned af[4][4], bf[2][2];
#pragma unroll
            for (int mt = 0; mt < 4; ++mt) {
                int r = wm + mt * 16 + g;
                af[mt][0] = *reinterpret_cast<const unsigned*>(&As[r][kk + 2 * qd]);
                af[mt][1] = *reinterpret_cast<const unsigned*>(&As[r + 8][kk + 2 * qd]);
                af[mt][2] = *reinterpret_cast<const unsigned*>(&As[r][kk + 2 * qd + 8]);
                af[mt][3] = *reinterpret_cast<const unsigned*>(&As[r + 8][kk + 2 * qd + 8]);
            }
#pragma unroll
            for (int nt = 0; nt < 2; ++nt) {
                int cn = wn + nt * 8 + g;
                bf[nt][0] = *reinterpret_cast<const unsigned*>(&Bs[cn][kk + 2 * qd]);
                bf[nt][1] = *reinterpret_cast<const unsigned*>(&Bs[cn][kk + 2 * qd + 8]);
            }
#pragma unroll
            for (int mt = 0; mt < 4; ++mt)
#pragma unroll
                for (int nt = 0; nt < 2; ++nt) mma_f16(c[mt][nt], af[mt], bf[nt]);
        }
        __syncthreads();
    }

#pragma unroll
    for (int mt = 0; mt < 4; ++mt) {
#pragma unroll
        for (int i = 0; i < 2; ++i) {
            int row = q0 + wm + mt * 16 + g + 8 * i;
#pragma unroll
            for (int nt = 0; nt < 2; ++nt) {
                int col = wn + nt * 8 + 2 * qd;
                float2 v;
                v.x = c[mt][nt][2 * i + 0];
                v.y = c[mt][nt][2 * i + 1];
                *reinterpret_cast<float2*>(ctx + ((size_t)b * Sv + row) * Dv + h * DHv + col) = v;
            }
        }
    }
}

// ---------------- LayerNorm over last dim (768) -------------------------------
__global__ __launch_bounds__(256) void layernorm_row(
    const float* __restrict__ pre, const float* __restrict__ w,
    const float* __restrict__ bb, float* __restrict__ out)
{
    __shared__ float red[9];
    const int t = threadIdx.x;
    const size_t row = blockIdx.x;
    const float* x = pre + row * Dv;

    float v[3];
#pragma unroll
    for (int j = 0; j < 3; ++j) v[j] = x[t + 256 * j];
    float s = v[0] + v[1] + v[2];
    s = blockReduce256(s, false, red);
    float u = s * (1.f / 768.f);
    float d0 = v[0] - u, d1 = v[1] - u, d2 = v[2] - u;
    float sq = d0 * d0 + d1 * d1 + d2 * d2;
    sq = blockReduce256(sq, false, red);
    float var = sq * (1.f / 768.f);
    float rr = rsqrtf(var + 1e-12f);
    float dd[3] = {d0, d1, d2};
#pragma unroll
    for (int j = 0; j < 3; ++j) {
        int ci = t + 256 * j;
        out[row * Dv + ci] = dd[j] * rr * w[ci] + bb[ci];
    }
}

// ------------------------------------------------------------------------------
extern "C" void kernel_launch(void* const* d_in, const int* in_sizes, int n_in,
                              void* d_out, int out_size)
{
    const float* hidden = (const float*)d_in[0];
    const float* mask   = (const float*)d_in[1];
    const float* prev   = (const float*)d_in[2];
    const float* Wq = (const float*)d_in[3];
    const float* bq = (const float*)d_in[4];
    const float* Wk = (const float*)d_in[5];
    const float* bk = (const float*)d_in[6];
    const float* Wv = (const float*)d_in[7];
    const float* bvp = (const float*)d_in[8];
    const float* cw = (const float*)d_in[9];
    const float* cb = (const float*)d_in[10];
    const float* Wo = (const float*)d_in[11];
    const float* bo = (const float*)d_in[12];
    const float* lnw = (const float*)d_in[13];
    const float* lnb = (const float*)d_in[14];
    float* out = (float*)d_out;

    float *q, *k, *v, *ctx, *psum, *inv1;
    unsigned *wt;
    __half *att, *vt;
    cudaGetSymbolAddress((void**)&q,    g_q);
    cudaGetSymbolAddress((void**)&k,    g_k);
    cudaGetSymbolAddress((void**)&v,    g_v);
    cudaGetSymbolAddress((void**)&att,  g_att);
    cudaGetSymbolAddress((void**)&ctx,  g_ctx);
    cudaGetSymbolAddress((void**)&wt,   g_wt);
    cudaGetSymbolAddress((void**)&vt,   g_vt);
    cudaGetSymbolAddress((void**)&psum, g_psum);
    cudaGetSymbolAddress((void**)&inv1, g_inv1);

    transpose_w4<<<dim3(24, 24, 4), 256>>>(Wq, Wk, Wv, Wo, wt);

    gemm_qkv<<<dim3(Dv / 128, Mv / 128, 3), 256>>>(hidden, wt, bq, bk, bvp, q, k, v);

    transpose_v_h<<<dim3(Sv / 32, DHv / 32, BHv), 256>>>(v, vt);

    qk_exp<<<dim3(Sv / 128, Sv / 128, BHv), 256>>>(q, k, mask, att, psum);

    stats_combine<<<(BHv * Sv) / 256, 256>>>(psum, inv1);

    mix2<<<dim3(Sv, Bv), 256>>>(att, prev, inv1, cw, cb);

    av_f16<<<dim3(Sv / 128, BHv), 256>>>(att, vt, ctx);

    gemm_out<<<dim3(Dv / 128, Mv / 128), 256>>>(ctx, wt + 3 * Dv * Dv, bo, hidden, q);

    layernorm_row<<<Mv, 256>>>(q, lnw, lnb, out);
}